// round 6
// baseline (speedup 1.0000x reference)
#include <cuda_runtime.h>
#include <cuda_bf16.h>
#include <cstdint>

// ---------------------------------------------------------------------------
// LSTM: batch=64, seq=512, input=512, hidden=512, fp32.
// Inputs: x [64,512,512], weight_ih [2048,512], weight_hh [2048,512],
//         bias_ih [2048], bias_hh [2048].
// Output: hidden_seq [64,512,512], h_f [64,512], c_f [64,512].
// ---------------------------------------------------------------------------

#define BATCH 64
#define SEQ   512
#define ISZ   512
#define HS    512
#define GATES (4 * HS)   // 2048

__device__ float g_xproj[(size_t)SEQ * BATCH * GATES];   // 256 MB scratch
__device__ float g_h[2][HS][BATCH];                      // transposed h, double buffer
__device__ unsigned g_count;                             // grid barrier arrivals
__device__ unsigned g_release;                           // grid barrier epoch

// ---------------- packed f32x2 helpers ----------------
__device__ __forceinline__ unsigned long long bcast2(float x) {
    unsigned long long r; unsigned u = __float_as_uint(x);
    asm("mov.b64 %0, {%1, %1};" : "=l"(r) : "r"(u));
    return r;
}
__device__ __forceinline__ void fma2(unsigned long long &acc,
                                     unsigned long long a, unsigned long long b) {
    asm("fma.rn.f32x2 %0, %1, %2, %0;" : "+l"(acc) : "l"(a), "l"(b));
}
__device__ __forceinline__ float2 unpack2(unsigned long long v) {
    unsigned lo, hi;
    asm("mov.b64 {%0, %1}, %2;" : "=r"(lo), "=r"(hi) : "l"(v));
    return make_float2(__uint_as_float(lo), __uint_as_float(hi));
}

// ---------------- cp.async helpers ----------------
__device__ __forceinline__ void cp_async16(unsigned smem_addr, const void* gptr) {
    asm volatile("cp.async.ca.shared.global [%0], [%1], 16;"
                 :: "r"(smem_addr), "l"(gptr));
}
__device__ __forceinline__ void cp_commit() {
    asm volatile("cp.async.commit_group;");
}
template <int N>
__device__ __forceinline__ void cp_wait() {
    asm volatile("cp.async.wait_group %0;" :: "n"(N));
}

// ===========================================================================
// Kernel 0: reset barrier state (every graph replay)
// ===========================================================================
__global__ void init_barrier_kernel() {
    g_count = 0u;
    g_release = 0u;
}

// ===========================================================================
// Kernel 1: x_proj GEMM, 128x128x8 tile, f32x2 packed math.
// ===========================================================================
#define GBM 128
#define GBN 128
#define GBK 8

__global__ __launch_bounds__(256, 2)
void xproj_gemm_kernel(const float* __restrict__ x,
                       const float* __restrict__ wih,
                       const float* __restrict__ bih,
                       const float* __restrict__ bhh)
{
    __shared__ float As[GBK][GBM];
    __shared__ float Bs[GBK][GBN];

    const int tid = threadIdx.x;
    const int m0 = blockIdx.y * GBM;
    const int n0 = blockIdx.x * GBN;

    const int lrow = tid >> 1;
    const int lk4  = (tid & 1) * 4;

    const int tx = tid & 15;
    const int ty = tid >> 4;

    unsigned long long acc2[8][4];
#pragma unroll
    for (int i = 0; i < 8; i++)
#pragma unroll
        for (int j2 = 0; j2 < 4; j2++) acc2[i][j2] = 0ull;

    const float* Aptr = x   + (size_t)(m0 + lrow) * ISZ + lk4;
    const float* Bptr = wih + (size_t)(n0 + lrow) * ISZ + lk4;

    float4 pa = *(const float4*)Aptr;
    float4 pb = *(const float4*)Bptr;

    const int NTK = ISZ / GBK;
    for (int t = 0; t < NTK; t++) {
        As[lk4 + 0][lrow] = pa.x; As[lk4 + 1][lrow] = pa.y;
        As[lk4 + 2][lrow] = pa.z; As[lk4 + 3][lrow] = pa.w;
        Bs[lk4 + 0][lrow] = pb.x; Bs[lk4 + 1][lrow] = pb.y;
        Bs[lk4 + 2][lrow] = pb.z; Bs[lk4 + 3][lrow] = pb.w;
        __syncthreads();

        if (t + 1 < NTK) {
            pa = *(const float4*)(Aptr + (t + 1) * GBK);
            pb = *(const float4*)(Bptr + (t + 1) * GBK);
        }

#pragma unroll
        for (int kk = 0; kk < GBK; kk++) {
            unsigned long long a2[8], b2[4];
#pragma unroll
            for (int i = 0; i < 8; i++) a2[i] = bcast2(As[kk][ty * 8 + i]);
#pragma unroll
            for (int j2 = 0; j2 < 4; j2++)
                b2[j2] = *(const unsigned long long*)&Bs[kk][tx * 8 + j2 * 2];
#pragma unroll
            for (int i = 0; i < 8; i++)
#pragma unroll
                for (int j2 = 0; j2 < 4; j2++)
                    fma2(acc2[i][j2], a2[i], b2[j2]);
        }
        __syncthreads();
    }

    float bsum[8];
#pragma unroll
    for (int j = 0; j < 8; j++) {
        int n = n0 + tx * 8 + j;
        bsum[j] = bih[n] + bhh[n];
    }

#pragma unroll
    for (int i = 0; i < 8; i++) {
        int m = m0 + ty * 8 + i;
        int b = m >> 9;
        int s = m & 511;
        float* orow = g_xproj + ((size_t)s * BATCH + b) * GATES + n0 + tx * 8;
#pragma unroll
        for (int j2 = 0; j2 < 4; j2 += 2) {
            float2 f0 = unpack2(acc2[i][j2 + 0]);
            float2 f1 = unpack2(acc2[i][j2 + 1]);
            float4 v;
            v.x = f0.x + bsum[j2 * 2 + 0];
            v.y = f0.y + bsum[j2 * 2 + 1];
            v.z = f1.x + bsum[j2 * 2 + 2];
            v.w = f1.y + bsum[j2 * 2 + 3];
            *(float4*)(orow + j2 * 2) = v;
        }
    }
}

// ===========================================================================
// Kernel 2: persistent recurrence. 128 blocks (1/SM), 512 threads.
// Block = 8 hidden units (j0..j0+7, all 4 gates = 32 W rows) x 32 batches
// (bhalf). Thread = (jg=gate, bgi=batch-octet, ksub=k-slice of 32).
// Thread tile 8 W-rows x 8 batches, f32x2 over batch pairs.
// W_s and h_s stored k-major for 128-bit conflict-free LDS.
// h staged via chunked cp.async overlapped with first-half compute.
// ===========================================================================
#define NB   128
#define NT   512
#define KST  36                    // k-major row stride (36 floats = 144 B, 16B-aligned)
#define SMW  (HS * KST)            // W_s floats: [512][36] (cols 0..31 used)
#define SMH  (HS * KST)            // h_s floats: [512][36] (cols 0..31 used)
#define SMRED (16 * 4 * 4 * 64)    // red floats: [w16][jg4][bgi4][pi4*wr8*el2]
#define PERS_SMEM_BYTES ((SMW + SMH + SMRED) * 4)   // 212,992 B

__device__ __forceinline__ float fsigmoid(float x) {
    return 1.f / (1.f + __expf(-x));
}
__device__ __forceinline__ float ftanh_fast(float x) {
    return 2.f / (1.f + __expf(-2.f * x)) - 1.f;
}

__global__ __launch_bounds__(NT, 1)
void lstm_persistent_kernel(const float* __restrict__ whh,
                            float* __restrict__ out,
                            float* __restrict__ hf_out,
                            float* __restrict__ cf_out)
{
    extern __shared__ float sm[];
    float* W_s = sm;                 // [k][row], row = g*8 + jl
    float* h_s = sm + SMW;           // [k][b],  b local 0..31
    float* red = sm + SMW + SMH;

    const int tid = threadIdx.x;
    const int j0    = (blockIdx.x >> 1) * 8;
    const int bhalf = blockIdx.x & 1;

    // ---- stage W_hh once, transposed to k-major ----
    for (int t = tid; t < 32 * 128; t += NT) {
        int row = t >> 7;              // 0..31 = g*8 + jl
        int k4  = (t & 127) << 2;
        int g = row >> 3, jl = row & 7;
        float4 v = *(const float4*)(whh + (size_t)(g * HS + j0 + jl) * HS + k4);
        W_s[(k4 + 0) * KST + row] = v.x;
        W_s[(k4 + 1) * KST + row] = v.y;
        W_s[(k4 + 2) * KST + row] = v.z;
        W_s[(k4 + 3) * KST + row] = v.w;
    }
    __syncthreads();

    const int jg   = tid & 3;          // gate
    const int bgi  = (tid >> 2) & 3;   // batch octet
    const int ksub = tid >> 4;         // 0..31
    const int lane = tid & 31;
    const int warp = tid >> 5;         // = ksub>>1

    // cell-update mapping (threads 0..255)
    const int ujl = tid & 7;           // j within block
    const int ubL = tid >> 3;          // local batch 0..31
    const int uj  = j0 + ujl;
    const int ub  = bhalf * 32 + ubL;
    const int bgi_f = ubL >> 3;
    const int pi_f  = (ubL & 7) >> 1;
    const int el_f  = ubL & 1;
    float c_reg = 0.f;

    const unsigned h_s_base = (unsigned)__cvta_generic_to_shared(h_s);

    for (int s = 0; s < SEQ; s++) {
        // prefetch x_proj (hides DRAM latency behind staging+compute)
        float xp0 = 0.f, xp1 = 0.f, xp2 = 0.f, xp3 = 0.f;
        if (tid < 256) {
            const float* xp = g_xproj + ((size_t)s * BATCH + ub) * GATES;
            xp0 = xp[0 * HS + uj];
            xp1 = xp[1 * HS + uj];
            xp2 = xp[2 * HS + uj];
            xp3 = xp[3 * HS + uj];
        }

        float gsum[4] = {0.f, 0.f, 0.f, 0.f};

        if (s > 0) {
            // ---- stage h_{s-1} via chunked cp.async: 4096 x 16B total ----
            // i = tid + iter*512: k = i>>3, c = (i&7)*4; iters 0..3 -> k<256
            const float* hsrc = &g_h[(s + 1) & 1][0][bhalf * 32];
#pragma unroll
            for (int it = 0; it < 4; it++) {
                int i = tid + it * NT;
                int k = i >> 3, c = (i & 7) << 2;
                cp_async16(h_s_base + (unsigned)(k * KST + c) * 4u,
                           hsrc + (size_t)k * BATCH + c);
            }
            cp_commit();
#pragma unroll
            for (int it = 4; it < 8; it++) {
                int i = tid + it * NT;
                int k = i >> 3, c = (i & 7) << 2;
                cp_async16(h_s_base + (unsigned)(k * KST + c) * 4u,
                           hsrc + (size_t)k * BATCH + c);
            }
            cp_commit();

            unsigned long long acc[4][8];
#pragma unroll
            for (int pi = 0; pi < 4; pi++)
#pragma unroll
                for (int wr = 0; wr < 8; wr++) acc[pi][wr] = 0ull;

            // ---- first half: k < 256 ----
            cp_wait<1>();
            __syncthreads();
#pragma unroll 4
            for (int r = 0; r < 8; r++) {
                int k = ksub + (r << 5);
                float4 w0 = *(const float4*)&W_s[k * KST + jg * 8];
                float4 w1 = *(const float4*)&W_s[k * KST + jg * 8 + 4];
                ulonglong2 ha = *(const ulonglong2*)&h_s[k * KST + bgi * 8];
                ulonglong2 hb = *(const ulonglong2*)&h_s[k * KST + bgi * 8 + 4];
                float wv[8] = {w0.x, w0.y, w0.z, w0.w, w1.x, w1.y, w1.z, w1.w};
#pragma unroll
                for (int wr = 0; wr < 8; wr++) {
                    unsigned long long w2 = bcast2(wv[wr]);
                    fma2(acc[0][wr], ha.x, w2);
                    fma2(acc[1][wr], ha.y, w2);
                    fma2(acc[2][wr], hb.x, w2);
                    fma2(acc[3][wr], hb.y, w2);
                }
            }

            // ---- second half: k >= 256 ----
            cp_wait<0>();
            __syncthreads();
#pragma unroll 4
            for (int r = 8; r < 16; r++) {
                int k = ksub + (r << 5);
                float4 w0 = *(const float4*)&W_s[k * KST + jg * 8];
                float4 w1 = *(const float4*)&W_s[k * KST + jg * 8 + 4];
                ulonglong2 ha = *(const ulonglong2*)&h_s[k * KST + bgi * 8];
                ulonglong2 hb = *(const ulonglong2*)&h_s[k * KST + bgi * 8 + 4];
                float wv[8] = {w0.x, w0.y, w0.z, w0.w, w1.x, w1.y, w1.z, w1.w};
#pragma unroll
                for (int wr = 0; wr < 8; wr++) {
                    unsigned long long w2 = bcast2(wv[wr]);
                    fma2(acc[0][wr], ha.x, w2);
                    fma2(acc[1][wr], ha.y, w2);
                    fma2(acc[2][wr], hb.x, w2);
                    fma2(acc[3][wr], hb.y, w2);
                }
            }

            // ---- butterfly over ksub parity (lane bit 4) ----
#pragma unroll
            for (int pi = 0; pi < 4; pi++)
#pragma unroll
                for (int wr = 0; wr < 8; wr++) {
                    float2 f = unpack2(acc[pi][wr]);
                    f.x += __shfl_xor_sync(0xffffffffu, f.x, 16);
                    f.y += __shfl_xor_sync(0xffffffffu, f.y, 16);
                    if (lane < 16) {
                        // red[warp][jg][bgi][pi*8+wr][el]
                        int base = ((warp * 4 + jg) * 4 + bgi) * 64;
                        *(float2*)&red[base + (pi * 8 + wr) * 2] = f;
                    }
                }
            __syncthreads();

            // ---- final combine: 256 threads, one (b, j) each ----
            if (tid < 256) {
#pragma unroll
                for (int g = 0; g < 4; g++) {
                    float acc_f = 0.f;
#pragma unroll
                    for (int w = 0; w < 16; w++)
                        acc_f += red[((w * 4 + g) * 4 + bgi_f) * 64
                                     + (pi_f * 8 + ujl) * 2 + el_f];
                    gsum[g] = acc_f;
                }
            }
        }

        // ---- cell update ----
        if (tid < 256) {
            float gi = gsum[0] + xp0;
            float gf = gsum[1] + xp1;
            float gc = gsum[2] + xp2;
            float go = gsum[3] + xp3;

            float i_ = fsigmoid(gi);
            float f_ = fsigmoid(gf);
            float g_ = ftanh_fast(gc);
            float o_ = fsigmoid(go);

            float cn = f_ * c_reg + i_ * g_;
            float hn = o_ * ftanh_fast(cn);
            c_reg = cn;

            out[((size_t)ub * SEQ + s) * HS + uj] = hn;
            g_h[s & 1][uj][ub] = hn;
            if (s == SEQ - 1 && hf_out != nullptr) {
                hf_out[ub * HS + uj] = hn;
                cf_out[ub * HS + uj] = cn;
            }
        }

        // ---- grid barrier (epoch s+1) ----
        __syncthreads();
        if (tid == 0) {
            __threadfence();
            unsigned prev = atomicAdd(&g_count, 1u);
            unsigned target = (unsigned)(s + 1);
            if (prev == target * NB - 1u) {
                atomicExch(&g_release, target);
            } else {
                unsigned r;
                do {
                    asm volatile("ld.acquire.gpu.u32 %0, [%1];" : "=r"(r) : "l"(&g_release));
                } while (r < target);
            }
        }
        __syncthreads();
    }
}

// ===========================================================================
// Launch
// ===========================================================================
extern "C" void kernel_launch(void* const* d_in, const int* in_sizes, int n_in,
                              void* d_out, int out_size)
{
    const float* x   = (const float*)d_in[0];
    const float* wih = (const float*)d_in[1];
    const float* whh = (const float*)d_in[2];
    const float* bih = (const float*)d_in[3];
    const float* bhh = (const float*)d_in[4];

    float* out = (float*)d_out;

    const size_t hidden_elems = (size_t)BATCH * SEQ * HS;
    float* hf = nullptr;
    float* cf = nullptr;
    if ((size_t)out_size >= hidden_elems + 2 * (size_t)BATCH * HS) {
        hf = out + hidden_elems;
        cf = hf + (size_t)BATCH * HS;
    }

    cudaFuncSetAttribute(lstm_persistent_kernel,
                         cudaFuncAttributeMaxDynamicSharedMemorySize,
                         PERS_SMEM_BYTES);

    init_barrier_kernel<<<1, 1>>>();

    dim3 ggrid(GATES / GBN, (BATCH * SEQ) / GBM);
    xproj_gemm_kernel<<<ggrid, 256>>>(x, wih, bih, bhh);

    lstm_persistent_kernel<<<NB, NT, PERS_SMEM_BYTES>>>(whh, out, hf, cf);
}

// round 7
// speedup vs baseline: 1.2162x; 1.2162x over previous
#include <cuda_runtime.h>
#include <cuda_bf16.h>
#include <cstdint>

// ---------------------------------------------------------------------------
// LSTM: batch=64, seq=512, input=512, hidden=512, fp32.
// Inputs: x [64,512,512], weight_ih [2048,512], weight_hh [2048,512],
//         bias_ih [2048], bias_hh [2048].
// Output: hidden_seq [64,512,512], h_f [64,512], c_f [64,512].
// ---------------------------------------------------------------------------

#define BATCH 64
#define SEQ   512
#define ISZ   512
#define HS    512
#define GATES (4 * HS)   // 2048

__device__ float g_xproj[(size_t)SEQ * BATCH * GATES];   // 256 MB scratch
__device__ float g_h[2][HS][BATCH];                      // transposed h, double buffer
__device__ unsigned g_count;                             // grid barrier arrivals
__device__ unsigned g_release;                           // grid barrier epoch

// ---------------- packed f32x2 helpers ----------------
__device__ __forceinline__ unsigned long long bcast2(float x) {
    unsigned long long r; unsigned u = __float_as_uint(x);
    asm("mov.b64 %0, {%1, %1};" : "=l"(r) : "r"(u));
    return r;
}
__device__ __forceinline__ void fma2(unsigned long long &acc,
                                     unsigned long long a, unsigned long long b) {
    asm("fma.rn.f32x2 %0, %1, %2, %0;" : "+l"(acc) : "l"(a), "l"(b));
}
__device__ __forceinline__ float2 unpack2(unsigned long long v) {
    unsigned lo, hi;
    asm("mov.b64 {%0, %1}, %2;" : "=r"(lo), "=r"(hi) : "l"(v));
    return make_float2(__uint_as_float(lo), __uint_as_float(hi));
}

// ===========================================================================
// Kernel 1: x_proj GEMM, 128x128x8 tile, f32x2 packed math.
// Also resets the grid-barrier state for the persistent kernel (stream-ordered
// before it), so there are exactly 2 launches per replay.
// ===========================================================================
#define GBM 128
#define GBN 128
#define GBK 8

__global__ __launch_bounds__(256, 2)
void xproj_gemm_kernel(const float* __restrict__ x,
                       const float* __restrict__ wih,
                       const float* __restrict__ bih,
                       const float* __restrict__ bhh)
{
    if (blockIdx.x == 0 && blockIdx.y == 0 && threadIdx.x == 0) {
        g_count = 0u;
        g_release = 0u;
    }

    __shared__ float As[GBK][GBM];
    __shared__ float Bs[GBK][GBN];

    const int tid = threadIdx.x;
    const int m0 = blockIdx.y * GBM;
    const int n0 = blockIdx.x * GBN;

    const int lrow = tid >> 1;
    const int lk4  = (tid & 1) * 4;

    const int tx = tid & 15;
    const int ty = tid >> 4;

    unsigned long long acc2[8][4];
#pragma unroll
    for (int i = 0; i < 8; i++)
#pragma unroll
        for (int j2 = 0; j2 < 4; j2++) acc2[i][j2] = 0ull;

    const float* Aptr = x   + (size_t)(m0 + lrow) * ISZ + lk4;
    const float* Bptr = wih + (size_t)(n0 + lrow) * ISZ + lk4;

    float4 pa = *(const float4*)Aptr;
    float4 pb = *(const float4*)Bptr;

    const int NTK = ISZ / GBK;
    for (int t = 0; t < NTK; t++) {
        As[lk4 + 0][lrow] = pa.x; As[lk4 + 1][lrow] = pa.y;
        As[lk4 + 2][lrow] = pa.z; As[lk4 + 3][lrow] = pa.w;
        Bs[lk4 + 0][lrow] = pb.x; Bs[lk4 + 1][lrow] = pb.y;
        Bs[lk4 + 2][lrow] = pb.z; Bs[lk4 + 3][lrow] = pb.w;
        __syncthreads();

        if (t + 1 < NTK) {
            pa = *(const float4*)(Aptr + (t + 1) * GBK);
            pb = *(const float4*)(Bptr + (t + 1) * GBK);
        }

#pragma unroll
        for (int kk = 0; kk < GBK; kk++) {
            unsigned long long a2[8], b2[4];
#pragma unroll
            for (int i = 0; i < 8; i++) a2[i] = bcast2(As[kk][ty * 8 + i]);
#pragma unroll
            for (int j2 = 0; j2 < 4; j2++)
                b2[j2] = *(const unsigned long long*)&Bs[kk][tx * 8 + j2 * 2];
#pragma unroll
            for (int i = 0; i < 8; i++)
#pragma unroll
                for (int j2 = 0; j2 < 4; j2++)
                    fma2(acc2[i][j2], a2[i], b2[j2]);
        }
        __syncthreads();
    }

    float bsum[8];
#pragma unroll
    for (int j = 0; j < 8; j++) {
        int n = n0 + tx * 8 + j;
        bsum[j] = bih[n] + bhh[n];
    }

#pragma unroll
    for (int i = 0; i < 8; i++) {
        int m = m0 + ty * 8 + i;
        int b = m >> 9;
        int s = m & 511;
        float* orow = g_xproj + ((size_t)s * BATCH + b) * GATES + n0 + tx * 8;
#pragma unroll
        for (int j2 = 0; j2 < 4; j2 += 2) {
            float2 f0 = unpack2(acc2[i][j2 + 0]);
            float2 f1 = unpack2(acc2[i][j2 + 1]);
            float4 v;
            v.x = f0.x + bsum[j2 * 2 + 0];
            v.y = f0.y + bsum[j2 * 2 + 1];
            v.z = f1.x + bsum[j2 * 2 + 2];
            v.w = f1.y + bsum[j2 * 2 + 3];
            *(float4*)(orow + j2 * 2) = v;
        }
    }
}

// ===========================================================================
// Kernel 2: persistent recurrence (round-5 structure + vectorized W loads).
// 128 blocks (1/SM), 512 threads. Block owns 4 hidden units (16 W rows),
// all 64 batches. W_hh resident in smem; c state in registers.
// Thread = (jl gate-col, ksub k-slice, bg batch-group); k blocked by 4 so the
// 4 gate-row weight reads are LDS.128.
// ===========================================================================
#define NB   128
#define NT   512
#define WSTR 520                 // padded W row stride (2080 B, 16B-aligned)
#define HTR  68                  // padded h row stride (272 B, 16B-aligned)
#define SMW  (16 * WSTR)         // 8320 floats
#define SMH  (HS * HTR)          // 34816 floats
#define SMRED (16 * 4 * 4 * 8)   // 2048 floats
#define PERS_SMEM_BYTES ((SMW + SMH + SMRED) * 4)   // 180,736 B

__device__ __forceinline__ float fsigmoid(float x) {
    return 1.f / (1.f + __expf(-x));
}
__device__ __forceinline__ float ftanh_fast(float x) {
    return 2.f / (1.f + __expf(-2.f * x)) - 1.f;
}

__global__ __launch_bounds__(NT, 1)
void lstm_persistent_kernel(const float* __restrict__ whh,
                            float* __restrict__ out,
                            float* __restrict__ hf_out,
                            float* __restrict__ cf_out)
{
    extern __shared__ float sm[];
    float* W_s = sm;                 // [16][WSTR], row = g*4 + jl
    float* h_s = sm + SMW;           // [512][HTR], [k][b]
    float* red = sm + SMW + SMH;     // [16][4][4][8]

    const int tid = threadIdx.x;
    const int j0 = blockIdx.x * 4;

    // ---- stage W_hh once for the whole sequence ----
    for (int t = tid; t < 16 * 128; t += NT) {
        int row = t >> 7;
        int kq = (t & 127) << 2;
        int g = row >> 2, jl = row & 3;
        float4 v = *(const float4*)(whh + (size_t)(g * HS + j0 + jl) * HS + kq);
        *(float4*)&W_s[row * WSTR + kq] = v;
    }
    __syncthreads();

    const int jl   = tid & 3;            // gate column within block
    const int ksub = (tid >> 2) & 15;    // k slice (x4 consecutive k)
    const int bg   = tid >> 6;           // batch group (8 batches)
    const int b0   = bg * 8;
    const int warp = tid >> 5;
    const int lane = tid & 31;

    // cell-update mapping (threads 0..255)
    const int ub = tid >> 2;             // batch
    const int uj = j0 + (tid & 3);       // hidden unit
    float c_reg = 0.f;

    for (int s = 0; s < SEQ; s++) {
        // prefetch x_proj values early (hides DRAM latency behind compute)
        float xp0 = 0.f, xp1 = 0.f, xp2 = 0.f, xp3 = 0.f;
        if (tid < 256) {
            const float* xp = g_xproj + ((size_t)s * BATCH + ub) * GATES;
            xp0 = xp[0 * HS + uj];
            xp1 = xp[1 * HS + uj];
            xp2 = xp[2 * HS + uj];
            xp3 = xp[3 * HS + uj];
        }

        float gsum[4] = {0.f, 0.f, 0.f, 0.f};

        if (s > 0) {
            // ---- stage h_{s-1}: g_h[(s-1)&1][k][b] -> h_s ----
            const float* hsrc = &g_h[(s + 1) & 1][0][0];
            for (int t = tid; t < (HS * BATCH) / 4; t += NT) {
                int k  = t >> 4;
                int c4 = (t & 15) << 2;
                float4 v = *(const float4*)(hsrc + k * BATCH + c4);
                *(float4*)&h_s[k * HTR + c4] = v;
            }
            __syncthreads();

            // ---- packed dot products: k blocked by 4; W via LDS.128 ----
            unsigned long long acc[4][4];
#pragma unroll
            for (int pi = 0; pi < 4; pi++)
#pragma unroll
                for (int g = 0; g < 4; g++) acc[pi][g] = 0ull;

#pragma unroll
            for (int r = 0; r < 8; r++) {
                int k = ksub * 4 + (r << 6);      // 4 consecutive k
                float4 wv[4];
#pragma unroll
                for (int g = 0; g < 4; g++)
                    wv[g] = *(const float4*)&W_s[(g * 4 + jl) * WSTR + k];
                float wf[4][4];
#pragma unroll
                for (int g = 0; g < 4; g++) {
                    wf[g][0] = wv[g].x; wf[g][1] = wv[g].y;
                    wf[g][2] = wv[g].z; wf[g][3] = wv[g].w;
                }
#pragma unroll
                for (int kk = 0; kk < 4; kk++) {
                    const float* hrow = &h_s[(k + kk) * HTR + b0];
                    unsigned long long w2[4];
#pragma unroll
                    for (int g = 0; g < 4; g++) w2[g] = bcast2(wf[g][kk]);
#pragma unroll
                    for (int pi = 0; pi < 4; pi++) {
                        unsigned long long h2 = *(const unsigned long long*)(hrow + pi * 2);
#pragma unroll
                        for (int g = 0; g < 4; g++) fma2(acc[pi][g], h2, w2[g]);
                    }
                }
            }

            // ---- butterfly over ksub low 3 bits (lane bits 2..4) ----
            float v[4][4][2];
#pragma unroll
            for (int pi = 0; pi < 4; pi++)
#pragma unroll
                for (int g = 0; g < 4; g++) {
                    float2 f = unpack2(acc[pi][g]);
                    v[pi][g][0] = f.x; v[pi][g][1] = f.y;
                }
#pragma unroll
            for (int off = 4; off <= 16; off <<= 1) {
#pragma unroll
                for (int pi = 0; pi < 4; pi++)
#pragma unroll
                    for (int g = 0; g < 4; g++) {
                        v[pi][g][0] += __shfl_xor_sync(0xffffffffu, v[pi][g][0], off);
                        v[pi][g][1] += __shfl_xor_sync(0xffffffffu, v[pi][g][1], off);
                    }
            }
            if (lane < 4) {   // lane == jl representative
#pragma unroll
                for (int pi = 0; pi < 4; pi++)
#pragma unroll
                    for (int g = 0; g < 4; g++) {
                        red[((warp * 4 + lane) * 4 + pi) * 8 + g * 2 + 0] = v[pi][g][0];
                        red[((warp * 4 + lane) * 4 + pi) * 8 + g * 2 + 1] = v[pi][g][1];
                    }
            }
            __syncthreads();

            if (tid < 256) {
                int cbg = ub >> 3;
                int cpi = (ub & 7) >> 1;
                int cel = ub & 1;
                int cjl = tid & 3;
                int w0 = cbg * 2, w1 = cbg * 2 + 1;
#pragma unroll
                for (int g = 0; g < 4; g++)
                    gsum[g] = red[((w0 * 4 + cjl) * 4 + cpi) * 8 + g * 2 + cel]
                            + red[((w1 * 4 + cjl) * 4 + cpi) * 8 + g * 2 + cel];
            }
        }

        // ---- cell update ----
        if (tid < 256) {
            float gi = gsum[0] + xp0;
            float gf = gsum[1] + xp1;
            float gc = gsum[2] + xp2;
            float go = gsum[3] + xp3;

            float i_ = fsigmoid(gi);
            float f_ = fsigmoid(gf);
            float g_ = ftanh_fast(gc);
            float o_ = fsigmoid(go);

            float cn = f_ * c_reg + i_ * g_;
            float hn = o_ * ftanh_fast(cn);
            c_reg = cn;

            out[((size_t)ub * SEQ + s) * HS + uj] = hn;
            g_h[s & 1][uj][ub] = hn;
            if (s == SEQ - 1 && hf_out != nullptr) {
                hf_out[ub * HS + uj] = hn;
                cf_out[ub * HS + uj] = cn;
            }
        }

        // ---- grid barrier (epoch s+1) ----
        __syncthreads();
        if (tid == 0) {
            __threadfence();
            unsigned prev = atomicAdd(&g_count, 1u);
            unsigned target = (unsigned)(s + 1);
            if (prev == target * NB - 1u) {
                atomicExch(&g_release, target);
            } else {
                unsigned r;
                do {
                    asm volatile("ld.acquire.gpu.u32 %0, [%1];" : "=r"(r) : "l"(&g_release));
                } while (r < target);
            }
        }
        __syncthreads();
    }
}

// ===========================================================================
// Launch
// ===========================================================================
extern "C" void kernel_launch(void* const* d_in, const int* in_sizes, int n_in,
                              void* d_out, int out_size)
{
    const float* x   = (const float*)d_in[0];
    const float* wih = (const float*)d_in[1];
    const float* whh = (const float*)d_in[2];
    const float* bih = (const float*)d_in[3];
    const float* bhh = (const float*)d_in[4];

    float* out = (float*)d_out;

    const size_t hidden_elems = (size_t)BATCH * SEQ * HS;
    float* hf = nullptr;
    float* cf = nullptr;
    if ((size_t)out_size >= hidden_elems + 2 * (size_t)BATCH * HS) {
        hf = out + hidden_elems;
        cf = hf + (size_t)BATCH * HS;
    }

    cudaFuncSetAttribute(lstm_persistent_kernel,
                         cudaFuncAttributeMaxDynamicSharedMemorySize,
                         PERS_SMEM_BYTES);

    // Phase 1: input projection GEMM (also resets grid-barrier state)
    dim3 ggrid(GATES / GBN, (BATCH * SEQ) / GBM);
    xproj_gemm_kernel<<<ggrid, 256>>>(x, wih, bih, bhh);

    // Phase 2: persistent recurrence (single launch, internal grid barriers)
    lstm_persistent_kernel<<<NB, NT, PERS_SMEM_BYTES>>>(whh, out, hf, cf);
}